// round 4
// baseline (speedup 1.0000x reference)
#include <cuda_runtime.h>

#define N_ELEMS 8192
#define NT 256
#define NB 128                      // blocks == chunks; one wave on 148 SMs
#define CHUNK 64                    // elems per block (NB*CHUNK = 8192)
#define NBUCK 20
#define TH 0.05f
#define JSPLIT 4
#define WCAP 4096

// ---- scratch (__device__ globals; no allocation allowed) ----
__device__ float g_spsi[N_ELEMS];
__device__ float g_sdd[N_ELEMS];
__device__ int   g_hist[NBUCK * NB];   // [bucket][chunk] for coalesced columns
__device__ float g_bce[NB];
__device__ float g_sd[NB];
__device__ float g_sd2[NB];
__device__ float g_psq[NB];
__device__ int   g_pcnt[NB];
__device__ unsigned g_bar_count;       // zero-init; returns to 0 each launch
__device__ unsigned g_bar_flag;        // generation counter; monotonic across replays

__device__ __forceinline__ float warp_sum_f(float v) {
#pragma unroll
    for (int o = 16; o > 0; o >>= 1) v += __shfl_down_sync(0xffffffffu, v, o);
    return v;
}
__device__ __forceinline__ int warp_sum_i(int v) {
#pragma unroll
    for (int o = 16; o > 0; o >>= 1) v += __shfl_down_sync(0xffffffffu, v, o);
    return v;
}
__device__ __forceinline__ int bucket_of(float p) {
    int b = (int)(p * 20.0f);
    return b > (NBUCK - 1) ? (NBUCK - 1) : b;
}

// Sense-reversing grid barrier. Generation counter survives graph replays
// (gen is read fresh each call; counter self-resets to 0 by the last arriver
// BEFORE the flag flips, so new-barrier arrivals always see 0).
__device__ __forceinline__ void grid_barrier(bool wait) {
    __syncthreads();
    if (threadIdx.x == 0) {
        unsigned gen = atomicAdd(&g_bar_flag, 0u);  // coherent read of generation
        __threadfence();                            // release my phase's writes
        unsigned old = atomicAdd(&g_bar_count, 1u);
        if (old == NB - 1) {
            atomicExch(&g_bar_count, 0u);
            __threadfence();
            atomicExch(&g_bar_flag, gen + 1u);      // release
        } else if (wait) {
            while (atomicAdd(&g_bar_flag, 0u) == gen) { }
        }
        __threadfence();                            // acquire others' writes
    }
    __syncthreads();
}

__global__ void __launch_bounds__(NT, 1)
fused_kernel(const float* __restrict__ pred,
             const float* __restrict__ psi,
             const int*   __restrict__ flag,
             float* __restrict__ out) {
    __shared__ float SP[WCAP];
    __shared__ float SD[WCAP];
    __shared__ int   h0[NBUCK], h1[NBUCK];
    __shared__ int   tot[NBUCK], myoff_s[NBUCK], base[NBUCK + 1];
    __shared__ float rf1[NT / 32], rf2[NT / 32], rf3[NT / 32];
    __shared__ int   ri1[NT / 32];
    __shared__ double dsq[4], dbce[4], dsd[4], dsd2[4];
    __shared__ long long dcnt[4];

    const int tid = threadIdx.x;
    const int blk = blockIdx.x;
    const int lane = tid & 31, warp = tid >> 5;
    const bool active = (tid < CHUNK);   // warps 0,1 fully active

    // ---------------- Phase 1: prep (d, bce terms, hist, ranks) ------------
    if (tid < NBUCK) { h0[tid] = 0; h1[tid] = 0; }
    __syncthreads();

    float t = 0.0f, d = 0.0f, term = 0.0f;
    int b = 0, rank = 0;
    if (active) {
        int i = blk * CHUNK + tid;
        float x = pred[i];
        t = psi[i];
        // stable BCE-with-logits term (fast math, err ~2^-22)
        term = fmaxf(x, 0.0f) - x * t + __logf(1.0f + __expf(-fabsf(x)));
        // logit with clamp [eps, 1-eps]
        float p = fminf(fmaxf(t, 1e-7f), 1.0f - 1e-7f);
        d = x - (__logf(p) - __logf(1.0f - p));
        b = bucket_of(t);
        unsigned m = __match_any_sync(0xffffffffu, b);
        int lr = __popc(m & ((1u << lane) - 1u));
        if (warp == 0) { if (lr == 0) h0[b] = __popc(m); }
        else           { if (lr == 0) h1[b] = __popc(m); }
        rank = lr;
    }
    __syncthreads();
    if (active && warp == 1) rank += h0[b];
    if (tid < NBUCK) g_hist[tid * NB + blk] = h0[tid] + h1[tid];

    // block partials: bce, sum d, sum d^2 (inactive threads contribute 0)
    {
        float s1 = warp_sum_f(term);
        float s2 = warp_sum_f(d);
        float s3 = warp_sum_f(d * d);
        if (lane == 0) { rf1[warp] = s1; rf2[warp] = s2; rf3[warp] = s3; }
        __syncthreads();
        if (tid == 0) {
            float a1 = 0, a2 = 0, a3 = 0;
#pragma unroll
            for (int w = 0; w < NT / 32; w++) { a1 += rf1[w]; a2 += rf2[w]; a3 += rf3[w]; }
            g_bce[blk] = a1; g_sd[blk] = a2; g_sd2[blk] = a3;
        }
    }

    grid_barrier(true);   // all hists visible

    // ---------------- Phase 2: per-block bucket prefix ----------------------
    if (tid < NBUCK) {
        const int* col = &g_hist[tid * NB];
        int s = 0, so = 0;
#pragma unroll 8
        for (int c = 0; c < NB; c++) {
            int v = col[c];
            s += v;
            if (c < blk) so += v;
        }
        tot[tid] = s;
        myoff_s[tid] = so;
    }
    __syncthreads();
    if (tid == 0) {
        int run = 0;
#pragma unroll
        for (int q = 0; q < NBUCK; q++) { base[q] = run; run += tot[q]; }
        base[NBUCK] = run;  // == N_ELEMS
    }
    __syncthreads();

    // ---------------- Phase 3: deterministic counting-sort scatter ----------
    if (active) {
        int pos = base[b] + myoff_s[b] + rank;
        g_spsi[pos] = t;
        g_sdd[pos]  = d;
    }

    grid_barrier(true);   // sorted arrays visible everywhere

    // ---------------- Phase 4: invalid pairs (|dpsi| < TH) ------------------
    // Block handles 64 consecutive sorted i's; window = buckets [b-1, b+1].
    const int i_base = blk * CHUNK;
    {
        float p_first = g_spsi[i_base];
        float p_last  = g_spsi[i_base + CHUNK - 1];
        int lo_b = max(bucket_of(p_first) - 1, 0);
        int hi_b = min(bucket_of(p_last) + 2, NBUCK);
        int wlo = base[lo_b], whi = base[hi_b];
        int wn = whi - wlo;
        bool use_s = (wn <= WCAP);
        if (use_s) {
            for (int k = tid; k < wn; k += NT) {
                SP[k] = g_spsi[wlo + k];
                SD[k] = g_sdd[wlo + k];
            }
        }
        __syncthreads();

        int il = tid & (CHUNK - 1);
        int js = tid >> 6;            // 4 j-splits
        int i = i_base + il;
        float pi = g_spsi[i];
        float di = g_sdd[i];
        int bi = bucket_of(pi);
        int lo = base[max(bi - 1, 0)] - wlo;
        int hi = base[min(bi + 2, NBUCK)] - wlo;

        float sq = 0.0f;
        int cnt = 0;
        if (use_s) {
#pragma unroll 4
            for (int k = lo + js; k < hi; k += JSPLIT) {
                float ori = pi - SP[k];
                if (fabsf(ori) < TH) {
                    float dd = di - SD[k];
                    sq = fmaf(dd, dd, sq);
                    cnt++;
                }
            }
        } else {
            for (int k = lo + js; k < hi; k += JSPLIT) {
                float ori = pi - g_spsi[wlo + k];
                if (fabsf(ori) < TH) {
                    float dd = di - g_sdd[wlo + k];
                    sq = fmaf(dd, dd, sq);
                    cnt++;
                }
            }
        }

        float s = warp_sum_f(sq);
        int c = warp_sum_i(cnt);
        if (lane == 0) { rf1[warp] = s; ri1[warp] = c; }
        __syncthreads();
        if (tid == 0) {
            float av = 0; int ac = 0;
#pragma unroll
            for (int w = 0; w < NT / 32; w++) { av += rf1[w]; ac += ri1[w]; }
            g_psq[blk] = av;
            g_pcnt[blk] = ac;
        }
    }

    // Blocks != 0 just arrive and exit; block 0 waits then finalizes.
    grid_barrier(blk == 0);
    if (blk != 0) return;

    // ---------------- Phase 5: final assembly (block 0) ---------------------
    {
        double sq = 0.0, bce = 0.0, sd = 0.0, sd2 = 0.0;
        long long cnt = 0;
        if (tid < NB) {
            sq   = (double)g_psq[tid];
            cnt  = (long long)g_pcnt[tid];
            bce  = (double)g_bce[tid];
            sd   = (double)g_sd[tid];
            sd2  = (double)g_sd2[tid];
        }
#pragma unroll
        for (int o = 16; o > 0; o >>= 1) {
            sq  += __shfl_down_sync(0xffffffffu, sq, o);
            cnt += __shfl_down_sync(0xffffffffu, cnt, o);
            bce += __shfl_down_sync(0xffffffffu, bce, o);
            sd  += __shfl_down_sync(0xffffffffu, sd, o);
            sd2 += __shfl_down_sync(0xffffffffu, sd2, o);
        }
        if (lane == 0 && warp < 4) {
            dsq[warp] = sq; dcnt[warp] = cnt; dbce[warp] = bce;
            dsd[warp] = sd; dsd2[warp] = sd2;
        }
        __syncthreads();
        if (tid == 0) {
            double SQ = 0, B = 0, SD = 0, SD2 = 0; long long C = 0;
#pragma unroll
            for (int w = 0; w < 4; w++) {
                SQ += dsq[w]; C += dcnt[w]; B += dbce[w];
                SD += dsd[w]; SD2 += dsd2[w];
            }
            // closed form over all pairs, subtract invalid contribution
            double Sall = 2.0 * (double)N_ELEMS * SD2 - 2.0 * SD * SD;
            long long nvalid = (long long)N_ELEMS * (long long)N_ELEMS - C;
            float loss = (float)(B / (double)N_ELEMS);
            float res = loss;
            if (*flag == 0 && nvalid > 0) {
                double mse = (Sall - SQ) / (double)nvalid;
                res = loss + 10.0f * (float)mse;
            }
            out[0] = res;
        }
    }
}

extern "C" void kernel_launch(void* const* d_in, const int* in_sizes, int n_in,
                              void* d_out, int out_size) {
    const float* pred = (const float*)d_in[0];
    const float* psi  = (const float*)d_in[1];
    const int*   flag = (const int*)d_in[2];
    float* out = (float*)d_out;

    fused_kernel<<<NB, NT>>>(pred, psi, flag, out);
}

// round 5
// speedup vs baseline: 1.0804x; 1.0804x over previous
#include <cuda_runtime.h>

#define N_ELEMS 8192
#define NT 256
#define NB 128                      // one wave on 148 SMs (33KB smem/block)
#define CHUNK 64                    // elems per block (NB*CHUNK = 8192)
#define NBUCK 20
#define TH 0.05f
#define JSPLIT 4
#define WCAP 4096

// ---- scratch (__device__ globals; no allocation allowed) ----
__device__ float g_spsi[N_ELEMS];
__device__ float g_sdd[N_ELEMS];
__device__ int   g_hist[NBUCK * NB];   // [bucket][block], coalesced columns
__device__ float g_bce[NB];
__device__ float g_sd[NB];
__device__ float g_sd2[NB];
__device__ float g_psq[NB];
__device__ int   g_pcnt[NB];
__device__ unsigned g_bar_count;       // self-resets to 0 each barrier
__device__ unsigned g_bar_flag;        // monotonic generation (survives replays)
__device__ unsigned g_done_count;      // last-block ticket; self-resets

__device__ __forceinline__ float warp_sum_f(float v) {
#pragma unroll
    for (int o = 16; o > 0; o >>= 1) v += __shfl_down_sync(0xffffffffu, v, o);
    return v;
}
__device__ __forceinline__ int warp_sum_i(int v) {
#pragma unroll
    for (int o = 16; o > 0; o >>= 1) v += __shfl_down_sync(0xffffffffu, v, o);
    return v;
}
__device__ __forceinline__ int bucket_of(float p) {
    int b = (int)(p * 20.0f);
    return b > (NBUCK - 1) ? (NBUCK - 1) : b;
}

// Grid barrier: arrival via ONE atomicAdd; spin via plain volatile L2 loads
// (no RMW in the poll loop -> no per-address atomic serialization).
// Generation counter is monotonic across graph replays; count self-resets
// before the flag flips, so next-barrier arrivals always see 0.
__device__ __forceinline__ void grid_barrier() {
    __syncthreads();
    if (threadIdx.x == 0) {
        volatile unsigned* vflag = &g_bar_flag;
        unsigned gen = *vflag;          // current generation (pre-arrival read)
        __threadfence();                // release this block's phase writes
        unsigned old = atomicAdd(&g_bar_count, 1u);
        if (old == NB - 1) {
            atomicExch(&g_bar_count, 0u);
            __threadfence();
            atomicExch(&g_bar_flag, gen + 1u);   // release all
        } else {
            while (*vflag == gen) { }            // cheap read-only spin
        }
        __threadfence();                // acquire other blocks' writes
    }
    __syncthreads();
}

__global__ void __launch_bounds__(NT, 1)
fused_kernel(const float* __restrict__ pred,
             const float* __restrict__ psi,
             const int*   __restrict__ flag,
             float* __restrict__ out) {
    __shared__ float SP[WCAP];
    __shared__ float SD[WCAP];
    __shared__ int   h0[NBUCK], h1[NBUCK];
    __shared__ int   tot[NBUCK], myoff_s[NBUCK], base[NBUCK + 1];
    __shared__ float rf1[NT / 32], rf2[NT / 32], rf3[NT / 32];
    __shared__ int   ri1[NT / 32];
    __shared__ int   s_is_last;
    __shared__ double dsq[4], dbce[4], dsd[4], dsd2[4];
    __shared__ long long dcnt[4];

    const int tid = threadIdx.x;
    const int blk = blockIdx.x;
    const int lane = tid & 31, warp = tid >> 5;
    const bool active = (tid < CHUNK);   // warps 0,1 fully active

    // ---------------- Phase 1: prep (d, bce terms, hist, ranks) ------------
    if (tid < NBUCK) { h0[tid] = 0; h1[tid] = 0; }
    __syncthreads();

    float t = 0.0f, d = 0.0f, term = 0.0f;
    int b = 0, rank = 0;
    if (active) {
        int i = blk * CHUNK + tid;
        float x = pred[i];
        t = psi[i];
        // stable BCE-with-logits term (fast math, err ~2^-22)
        term = fmaxf(x, 0.0f) - x * t + __logf(1.0f + __expf(-fabsf(x)));
        // logit with clamp [eps, 1-eps]
        float p = fminf(fmaxf(t, 1e-7f), 1.0f - 1e-7f);
        d = x - (__logf(p) - __logf(1.0f - p));
        b = bucket_of(t);
        unsigned m = __match_any_sync(0xffffffffu, b);
        int lr = __popc(m & ((1u << lane) - 1u));
        if (warp == 0) { if (lr == 0) h0[b] = __popc(m); }
        else           { if (lr == 0) h1[b] = __popc(m); }
        rank = lr;
    }
    __syncthreads();
    if (active && warp == 1) rank += h0[b];
    if (tid < NBUCK) g_hist[tid * NB + blk] = h0[tid] + h1[tid];

    {   // block partials: bce, sum d, sum d^2
        float s1 = warp_sum_f(term);
        float s2 = warp_sum_f(d);
        float s3 = warp_sum_f(d * d);
        if (lane == 0) { rf1[warp] = s1; rf2[warp] = s2; rf3[warp] = s3; }
        __syncthreads();
        if (tid == 0) {
            float a1 = 0, a2 = 0, a3 = 0;
#pragma unroll
            for (int w = 0; w < NT / 32; w++) { a1 += rf1[w]; a2 += rf2[w]; a3 += rf3[w]; }
            g_bce[blk] = a1; g_sd[blk] = a2; g_sd2[blk] = a3;
        }
    }

    grid_barrier();   // all hists visible

    // ---------------- Phase 2: per-block bucket prefix ----------------------
    if (tid < NBUCK) {
        const int* col = &g_hist[tid * NB];
        int s = 0, so = 0;
#pragma unroll 8
        for (int c = 0; c < NB; c++) {
            int v = col[c];
            s += v;
            if (c < blk) so += v;
        }
        tot[tid] = s;
        myoff_s[tid] = so;
    }
    __syncthreads();
    if (tid == 0) {
        int run = 0;
#pragma unroll
        for (int q = 0; q < NBUCK; q++) { base[q] = run; run += tot[q]; }
        base[NBUCK] = run;  // == N_ELEMS
    }
    __syncthreads();

    // ---------------- Phase 3: deterministic counting-sort scatter ----------
    if (active) {
        int pos = base[b] + myoff_s[b] + rank;
        g_spsi[pos] = t;
        g_sdd[pos]  = d;
    }

    grid_barrier();   // sorted arrays visible everywhere

    // ---------------- Phase 4: invalid pairs (|dpsi| < TH) ------------------
    const int i_base = blk * CHUNK;
    {
        float p_first = g_spsi[i_base];
        float p_last  = g_spsi[i_base + CHUNK - 1];
        int lo_b = max(bucket_of(p_first) - 1, 0);
        int hi_b = min(bucket_of(p_last) + 2, NBUCK);
        int wlo = base[lo_b], whi = base[hi_b];
        int wn = whi - wlo;
        bool use_s = (wn <= WCAP);
        if (use_s) {
            for (int k = tid; k < wn; k += NT) {
                SP[k] = g_spsi[wlo + k];
                SD[k] = g_sdd[wlo + k];
            }
        }
        __syncthreads();

        int il = tid & (CHUNK - 1);
        int js = tid >> 6;            // 4 j-splits
        int i = i_base + il;
        float pi = g_spsi[i];
        float di = g_sdd[i];
        int bi = bucket_of(pi);
        int lo = base[max(bi - 1, 0)] - wlo;
        int hi = base[min(bi + 2, NBUCK)] - wlo;

        float sq = 0.0f;
        int cnt = 0;
        if (use_s) {
#pragma unroll 4
            for (int k = lo + js; k < hi; k += JSPLIT) {
                float ori = pi - SP[k];
                if (fabsf(ori) < TH) {
                    float dd = di - SD[k];
                    sq = fmaf(dd, dd, sq);
                    cnt++;
                }
            }
        } else {
            for (int k = lo + js; k < hi; k += JSPLIT) {
                float ori = pi - g_spsi[wlo + k];
                if (fabsf(ori) < TH) {
                    float dd = di - g_sdd[wlo + k];
                    sq = fmaf(dd, dd, sq);
                    cnt++;
                }
            }
        }

        float s = warp_sum_f(sq);
        int c = warp_sum_i(cnt);
        if (lane == 0) { rf1[warp] = s; ri1[warp] = c; }
        __syncthreads();
        if (tid == 0) {
            float av = 0; int ac = 0;
#pragma unroll
            for (int w = 0; w < NT / 32; w++) { av += rf1[w]; ac += ri1[w]; }
            g_psq[blk] = av;
            g_pcnt[blk] = ac;
        }
    }

    // ---------------- Last-block-done ticket (replaces 3rd barrier) ---------
    if (tid == 0) {
        __threadfence();                         // release g_psq/g_pcnt
        unsigned tk = atomicAdd(&g_done_count, 1u);
        s_is_last = (tk == NB - 1);
    }
    __syncthreads();
    if (!s_is_last) return;
    if (tid == 0) atomicExch(&g_done_count, 0u); // reset for next replay
    __threadfence();                             // acquire all partials
    __syncthreads();

    // ---------------- Phase 5: final assembly (last block) ------------------
    {
        double sq = 0.0, bce = 0.0, sd = 0.0, sd2 = 0.0;
        long long cnt = 0;
        if (tid < NB) {
            sq   = (double)g_psq[tid];
            cnt  = (long long)g_pcnt[tid];
            bce  = (double)g_bce[tid];
            sd   = (double)g_sd[tid];
            sd2  = (double)g_sd2[tid];
        }
#pragma unroll
        for (int o = 16; o > 0; o >>= 1) {
            sq  += __shfl_down_sync(0xffffffffu, sq, o);
            cnt += __shfl_down_sync(0xffffffffu, cnt, o);
            bce += __shfl_down_sync(0xffffffffu, bce, o);
            sd  += __shfl_down_sync(0xffffffffu, sd, o);
            sd2 += __shfl_down_sync(0xffffffffu, sd2, o);
        }
        if (lane == 0 && warp < 4) {
            dsq[warp] = sq; dcnt[warp] = cnt; dbce[warp] = bce;
            dsd[warp] = sd; dsd2[warp] = sd2;
        }
        __syncthreads();
        if (tid == 0) {
            double SQ = 0, B = 0, SD = 0, SD2 = 0; long long C = 0;
#pragma unroll
            for (int w = 0; w < 4; w++) {
                SQ += dsq[w]; C += dcnt[w]; B += dbce[w];
                SD += dsd[w]; SD2 += dsd2[w];
            }
            // closed form over all pairs, minus invalid contribution
            double Sall = 2.0 * (double)N_ELEMS * SD2 - 2.0 * SD * SD;
            long long nvalid = (long long)N_ELEMS * (long long)N_ELEMS - C;
            float loss = (float)(B / (double)N_ELEMS);
            float res = loss;
            if (*flag == 0 && nvalid > 0) {
                double mse = (Sall - SQ) / (double)nvalid;
                res = loss + 10.0f * (float)mse;
            }
            out[0] = res;
        }
    }
}

extern "C" void kernel_launch(void* const* d_in, const int* in_sizes, int n_in,
                              void* d_out, int out_size) {
    const float* pred = (const float*)d_in[0];
    const float* psi  = (const float*)d_in[1];
    const int*   flag = (const int*)d_in[2];
    float* out = (float*)d_out;

    fused_kernel<<<NB, NT>>>(pred, psi, flag, out);
}

// round 7
// speedup vs baseline: 1.1780x; 1.0904x over previous
#include <cuda_runtime.h>

#define N_ELEMS 8192
#define NT 256
#define NBLK1 32                    // kernel-1 blocks (32 x 256 = 8192)
#define NBUCK 20
#define CAP 256                     // per-(bucket,block) segment capacity (worst case)
#define TH 0.05f
#define SPLITB 7                    // i-splits per bucket in kernel 2
#define NB2 (NBUCK * SPLITB)        // 140 blocks, one wave
#define JSPLIT 4
#define WCAP 4096
#define MAXSEG 96                   // <= 3 buckets x 32 segments

// ---- scratch (__device__ globals; no allocation allowed) ----
__device__ float g_seg_psi[NBUCK * NBLK1 * CAP];   // segmented by (bucket, block)
__device__ float g_seg_d[NBUCK * NBLK1 * CAP];
__device__ int   g_hist[NBUCK * NBLK1];            // [bucket][block]
__device__ float g_bce[NBLK1], g_sd[NBLK1], g_sd2[NBLK1];
__device__ float g_psq[NB2];
__device__ int   g_pcnt[NB2];
__device__ unsigned g_done;                        // ticket; self-resets each launch

__device__ __forceinline__ float warp_sum_f(float v) {
#pragma unroll
    for (int o = 16; o > 0; o >>= 1) v += __shfl_down_sync(0xffffffffu, v, o);
    return v;
}
__device__ __forceinline__ int warp_sum_i(int v) {
#pragma unroll
    for (int o = 16; o > 0; o >>= 1) v += __shfl_down_sync(0xffffffffu, v, o);
    return v;
}
__device__ __forceinline__ int bucket_of(float p) {
    int b = (int)(p * 20.0f);
    return b > (NBUCK - 1) ? (NBUCK - 1) : b;
}

// ---------------------------------------------------------------------------
// Kernel 1: prep + deterministic segmented bucket scatter + hist + O(N) sums.
// No cross-block communication; the kernel boundary is the sync.
// ---------------------------------------------------------------------------
__global__ void __launch_bounds__(NT, 1)
prep_scatter_kernel(const float* __restrict__ pred,
                    const float* __restrict__ psi) {
    __shared__ int   wcnt[NT / 32][NBUCK];
    __shared__ float rf1[NT / 32], rf2[NT / 32], rf3[NT / 32];

    const int tid = threadIdx.x, blk = blockIdx.x;
    const int lane = tid & 31, w = tid >> 5;

    if (tid < (NT / 32) * NBUCK) ((int*)wcnt)[tid] = 0;
    __syncthreads();

    int i = blk * NT + tid;
    float x = pred[i];
    float t = psi[i];

    // stable BCE-with-logits term (fast math, err ~2^-22)
    float term = fmaxf(x, 0.0f) - x * t + __logf(1.0f + __expf(-fabsf(x)));
    // logit with clamp [eps, 1-eps]
    float p = fminf(fmaxf(t, 1e-7f), 1.0f - 1e-7f);
    float d = x - (__logf(p) - __logf(1.0f - p));

    int b = bucket_of(t);
    unsigned m = __match_any_sync(0xffffffffu, b);
    int lr = __popc(m & ((1u << lane) - 1u));
    if (lr == 0) wcnt[w][b] = __popc(m);
    __syncthreads();

    int rank = lr;
#pragma unroll
    for (int ww = 0; ww < NT / 32; ww++)
        if (ww < w) rank += wcnt[ww][b];

    int pos = (b * NBLK1 + blk) * CAP + rank;   // rank < 256 == CAP always
    g_seg_psi[pos] = t;
    g_seg_d[pos]   = d;

    if (tid < NBUCK) {
        int s = 0;
#pragma unroll
        for (int ww = 0; ww < NT / 32; ww++) s += wcnt[ww][tid];
        g_hist[tid * NBLK1 + blk] = s;
    }

    // block partials for the closed form + BCE
    float s1 = warp_sum_f(term);
    float s2 = warp_sum_f(d);
    float s3 = warp_sum_f(d * d);
    if (lane == 0) { rf1[w] = s1; rf2[w] = s2; rf3[w] = s3; }
    __syncthreads();
    if (tid == 0) {
        float a1 = 0, a2 = 0, a3 = 0;
#pragma unroll
        for (int ww = 0; ww < NT / 32; ww++) { a1 += rf1[ww]; a2 += rf2[ww]; a3 += rf3[ww]; }
        g_bce[blk] = a1; g_sd[blk] = a2; g_sd2[blk] = a3;
    }
}

// ---------------------------------------------------------------------------
// Kernel 2: gather 3-bucket window -> smem, invalid-pair scan, ticket finalize.
// Block = (bucket b, split s). Deterministic i-partition: bucket-b elements at
// local indices s, s+7, s+14, ...
// ---------------------------------------------------------------------------
__global__ void __launch_bounds__(NT, 1)
pair_final_kernel(const int* __restrict__ flag, float* __restrict__ out) {
    __shared__ float SP[WCAP];
    __shared__ float SD[WCAP];
    __shared__ int   sh_cnt[MAXSEG], sh_off[MAXSEG];
    __shared__ float rf[NT / 32];
    __shared__ int   ri[NT / 32];
    __shared__ int   s_last;
    __shared__ double dsq[NT / 32], dbce[NT / 32], dsd[NT / 32], dsd2[NT / 32];
    __shared__ long long dcnt[NT / 32];

    const int tid = threadIdx.x;
    const int lane = tid & 31, w = tid >> 5;
    const int b = blockIdx.x / SPLITB;
    const int s = blockIdx.x % SPLITB;

    const int lo_b = max(b - 1, 0);
    const int hi_b = min(b + 2, NBUCK);
    const int nseg = (hi_b - lo_b) * NBLK1;

    if (tid < nseg) {
        int bw = lo_b + tid / NBLK1, sb = tid % NBLK1;
        sh_cnt[tid] = g_hist[bw * NBLK1 + sb];
    }
    __syncthreads();
    if (tid < nseg) {                 // exclusive prefix: thread j sums k<j
        int o = 0;
        for (int k = 0; k < nseg; k++)
            if (k < tid) o += sh_cnt[k];
        sh_off[tid] = o;
    }
    __syncthreads();
    const int wn = sh_off[nseg - 1] + sh_cnt[nseg - 1];
    const bool use_s = (wn <= WCAP);

    if (use_s) {
        // each warp copies segments w, w+8, ...
        for (int seg = w; seg < nseg; seg += NT / 32) {
            int c = sh_cnt[seg], o = sh_off[seg];
            int bw = lo_b + seg / NBLK1, sb = seg % NBLK1;
            const float* sp = &g_seg_psi[(bw * NBLK1 + sb) * CAP];
            const float* sd = &g_seg_d[(bw * NBLK1 + sb) * CAP];
            for (int k = lane; k < c; k += 32) {
                SP[o + k] = sp[k];
                SD[o + k] = sd[k];
            }
        }
    }
    __syncthreads();

    // bucket-b region inside the window (the i-elements)
    const int idxs = (b - lo_b) * NBLK1;
    const int istart = sh_off[idxs];
    const int iend = (idxs + NBLK1 < nseg) ? sh_off[idxs + NBLK1] : wn;
    const int cnt_b = iend - istart;

    const int il = tid & 63;          // 64 i-lanes
    const int js = tid >> 6;          // 4 j-splits (uniform per warp)

    // number of i's this block owns: indices s, s+7, ... < cnt_b
    int nmine = (cnt_b > s) ? (cnt_b - s + SPLITB - 1) / SPLITB : 0;

    float sq = 0.0f;
    int cnt = 0;
    if (use_s) {
        for (int idx = il; idx < nmine; idx += 64) {
            int iloc = s + idx * SPLITB;
            float pi = SP[istart + iloc];
            float di = SD[istart + iloc];
#pragma unroll 4
            for (int k = js; k < wn; k += JSPLIT) {
                float ori = pi - SP[k];
                if (fabsf(ori) < TH) {
                    float dv = di - SD[k];
                    sq = fmaf(dv, dv, sq);
                    cnt++;
                }
            }
        }
    } else {
        // correctness fallback: scan directly from global segments
        for (int idx = il; idx < nmine; idx += 64) {
            int iloc = s + idx * SPLITB;
            int rem = iloc, seg = idxs;
            while (rem >= sh_cnt[seg]) { rem -= sh_cnt[seg]; seg++; }
            int bw = lo_b + seg / NBLK1, sb = seg % NBLK1;
            float pi = g_seg_psi[(bw * NBLK1 + sb) * CAP + rem];
            float di = g_seg_d[(bw * NBLK1 + sb) * CAP + rem];
            for (int sg = 0; sg < nseg; sg++) {
                int c = sh_cnt[sg];
                int bw2 = lo_b + sg / NBLK1, sb2 = sg % NBLK1;
                const float* sp = &g_seg_psi[(bw2 * NBLK1 + sb2) * CAP];
                const float* sdp = &g_seg_d[(bw2 * NBLK1 + sb2) * CAP];
                for (int k = js; k < c; k += JSPLIT) {
                    float ori = pi - sp[k];
                    if (fabsf(ori) < TH) {
                        float dv = di - sdp[k];
                        sq = fmaf(dv, dv, sq);
                        cnt++;
                    }
                }
            }
        }
    }

    float sv = warp_sum_f(sq);
    int cv = warp_sum_i(cnt);
    if (lane == 0) { rf[w] = sv; ri[w] = cv; }
    __syncthreads();
    if (tid == 0) {
        float av = 0; int ac = 0;
#pragma unroll
        for (int ww = 0; ww < NT / 32; ww++) { av += rf[ww]; ac += ri[ww]; }
        g_psq[blockIdx.x] = av;
        g_pcnt[blockIdx.x] = ac;
    }

    // ---- last-block ticket -> finalize ----
    if (tid == 0) {
        __threadfence();                          // release partials
        unsigned tk = atomicAdd(&g_done, 1u);
        s_last = (tk == NB2 - 1);
    }
    __syncthreads();
    if (!s_last) return;
    if (tid == 0) atomicExch(&g_done, 0u);        // reset for next replay
    __threadfence();                              // acquire all partials
    __syncthreads();

    {
        double psq = 0.0, bce = 0.0, sd = 0.0, sd2 = 0.0;
        long long pc = 0;
        if (tid < NB2) {
            psq = (double)g_psq[tid];
            pc  = (long long)g_pcnt[tid];
        }
        if (tid < NBLK1) {
            bce = (double)g_bce[tid];
            sd  = (double)g_sd[tid];
            sd2 = (double)g_sd2[tid];
        }
#pragma unroll
        for (int o = 16; o > 0; o >>= 1) {
            psq += __shfl_down_sync(0xffffffffu, psq, o);
            pc  += __shfl_down_sync(0xffffffffu, pc, o);
            bce += __shfl_down_sync(0xffffffffu, bce, o);
            sd  += __shfl_down_sync(0xffffffffu, sd, o);
            sd2 += __shfl_down_sync(0xffffffffu, sd2, o);
        }
        if (lane == 0) {
            dsq[w] = psq; dcnt[w] = pc; dbce[w] = bce; dsd[w] = sd; dsd2[w] = sd2;
        }
        __syncthreads();
        if (tid == 0) {
            double SQ = 0, B = 0, SD = 0, SD2 = 0; long long C = 0;
#pragma unroll
            for (int ww = 0; ww < NT / 32; ww++) {
                SQ += dsq[ww]; C += dcnt[ww]; B += dbce[ww];
                SD += dsd[ww]; SD2 += dsd2[ww];
            }
            // closed form over all pairs, minus invalid contribution
            double Sall = 2.0 * (double)N_ELEMS * SD2 - 2.0 * SD * SD;
            long long nvalid = (long long)N_ELEMS * (long long)N_ELEMS - C;
            float loss = (float)(B / (double)N_ELEMS);
            float res = loss;
            if (*flag == 0 && nvalid > 0) {
                double mse = (Sall - SQ) / (double)nvalid;
                res = loss + 10.0f * (float)mse;
            }
            out[0] = res;
        }
    }
}

extern "C" void kernel_launch(void* const* d_in, const int* in_sizes, int n_in,
                              void* d_out, int out_size) {
    const float* pred = (const float*)d_in[0];
    const float* psi  = (const float*)d_in[1];
    const int*   flag = (const int*)d_in[2];
    float* out = (float*)d_out;

    prep_scatter_kernel<<<NBLK1, NT>>>(pred, psi);
    pair_final_kernel<<<NB2, NT>>>(flag, out);
}